// round 1
// baseline (speedup 1.0000x reference)
#include <cuda_runtime.h>
#include <math.h>

#define NB 2
#define NC 8
#define NF 1024
#define NW 512
#define NHEAD 8
#define NHD 128
#define NBC (NB*NC)
#define TENS ((size_t)NB*NC*NF*NW)          // 8388608
#define QKN  ((size_t)NB*NC*NHEAD*NW*NW)    // 33554432

// ---------------- scratch (static device globals; no runtime alloc) ----------------
__device__ float g_cq[NB*NC*NF*NW];
__device__ float g_ck[NB*NC*NF*NW];
__device__ float g_cv[NB*NC*NF*NW];
__device__ float g_q [NB*NC*NF*NW];
__device__ float g_k [NB*NC*NF*NW];
__device__ float g_v [NB*NC*NF*NW];
__device__ float g_a [NB*NC*NF*NW];

__device__ __forceinline__ const float* gemm_src(int s) {
    switch (s) { case 0: return g_cq; case 1: return g_ck; case 2: return g_cv; default: return g_a; }
}
__device__ __forceinline__ float* gemm_dst(int s, float* ext) {
    switch (s) { case 0: return g_q; case 1: return g_k; case 2: return g_v; default: return ext; }
}

// ---------------- fused 3x conv2d (3x3, pad 1, C=8 in/out) ----------------
// grid (NW/32, NF/32, NB), 256 threads; each thread computes 4 pixels x 8 co x 3 convs
__global__ void __launch_bounds__(256) conv3_kernel(
    const float* __restrict__ x,
    const float* __restrict__ wq, const float* __restrict__ bq,
    const float* __restrict__ wk, const float* __restrict__ bk,
    const float* __restrict__ wv, const float* __restrict__ bv)
{
    __shared__ float xs[NC][34][36];
    __shared__ float ws[3*NC*NC*9];     // wq | wk | wv
    int tid = threadIdx.x;
    int bxo = blockIdx.x * 32;          // w origin
    int byo = blockIdx.y * 32;          // h(f) origin
    int b   = blockIdx.z;

    for (int i = tid; i < NC*NC*9; i += 256) {
        ws[i]            = wq[i];
        ws[NC*NC*9 + i]  = wk[i];
        ws[2*NC*NC*9 + i]= wv[i];
    }
    for (int i = tid; i < NC*34*34; i += 256) {
        int ci = i / (34*34);
        int r  = (i / 34) % 34;
        int cl = i % 34;
        int gy = byo + r - 1, gx = bxo + cl - 1;
        float v = 0.f;
        if (gy >= 0 && gy < NF && gx >= 0 && gx < NW)
            v = x[(((size_t)b*NC + ci)*NF + gy)*NW + gx];
        xs[ci][r][cl] = v;
    }
    __syncthreads();

    #pragma unroll
    for (int p = 0; p < 4; ++p) {
        int pid = tid + p*256;
        int py = pid >> 5, px = pid & 31;
        float aq[NC], ak[NC], av[NC];
        #pragma unroll
        for (int co = 0; co < NC; ++co) { aq[co]=bq[co]; ak[co]=bk[co]; av[co]=bv[co]; }
        #pragma unroll
        for (int ci = 0; ci < NC; ++ci) {
            float w9[9];
            #pragma unroll
            for (int dy = 0; dy < 3; ++dy)
                #pragma unroll
                for (int dx = 0; dx < 3; ++dx)
                    w9[dy*3+dx] = xs[ci][py+dy][px+dx];
            #pragma unroll
            for (int co = 0; co < NC; ++co) {
                int wb = (co*NC + ci)*9;
                float sq=0.f, sk=0.f, sv=0.f;
                #pragma unroll
                for (int t = 0; t < 9; ++t) {
                    sq += w9[t]*ws[wb+t];
                    sk += w9[t]*ws[NC*NC*9 + wb+t];
                    sv += w9[t]*ws[2*NC*NC*9 + wb+t];
                }
                aq[co]+=sq; ak[co]+=sk; av[co]+=sv;
            }
        }
        int gy = byo + py, gx = bxo + px;
        #pragma unroll
        for (int co = 0; co < NC; ++co) {
            size_t o = (((size_t)b*NC+co)*NF + gy)*NW + gx;
            g_cq[o]=aq[co]; g_ck[o]=ak[co]; g_cv[o]=av[co];
        }
    }
}

// ---------------- mc_linear batched SGEMM ----------------
// Y[z][m][n] = sum_k W[z%NC][m][k] * B[z][k][n];  M=NF, N=NW, K=NF
// 128x128 tile, BK=8, 256 threads, 8x8 per-thread microtile
__global__ void __launch_bounds__(256) gemm_lin(
    const float* __restrict__ Wlin, int srcSel, int dstSel, float* __restrict__ dstExt)
{
    __shared__ float As[8][128];
    __shared__ float Bs[8][128];
    int z = blockIdx.z;
    const float* A  = Wlin + (size_t)(z % NC) * NF * NF;
    const float* Bm = gemm_src(srcSel) + (size_t)z * NF * NW;
    float*       Cm = gemm_dst(dstSel, dstExt) + (size_t)z * NF * NW;
    int m0 = blockIdx.y * 128;
    int n0 = blockIdx.x * 128;
    int tid = threadIdx.x;
    int ty = tid >> 4, tx = tid & 15;
    int arow = tid >> 1, acol = (tid & 1) * 4;
    int brow = tid >> 5, bcol = (tid & 31) * 4;

    float acc[8][8] = {};
    for (int k0 = 0; k0 < NF; k0 += 8) {
        float4 avv = *(const float4*)&A [(size_t)(m0 + arow)*NF + k0 + acol];
        float4 bvv = *(const float4*)&Bm[(size_t)(k0 + brow)*NW + n0 + bcol];
        As[acol+0][arow]=avv.x; As[acol+1][arow]=avv.y;
        As[acol+2][arow]=avv.z; As[acol+3][arow]=avv.w;
        *(float4*)&Bs[brow][bcol] = bvv;
        __syncthreads();
        #pragma unroll
        for (int kk = 0; kk < 8; ++kk) {
            float a[8], bb[8];
            *(float4*)&a[0]  = *(const float4*)&As[kk][ty*8];
            *(float4*)&a[4]  = *(const float4*)&As[kk][ty*8+4];
            *(float4*)&bb[0] = *(const float4*)&Bs[kk][tx*8];
            *(float4*)&bb[4] = *(const float4*)&Bs[kk][tx*8+4];
            #pragma unroll
            for (int i = 0; i < 8; ++i)
                #pragma unroll
                for (int j = 0; j < 8; ++j)
                    acc[i][j] += a[i]*bb[j];
        }
        __syncthreads();
    }
    #pragma unroll
    for (int i = 0; i < 8; ++i) {
        size_t row = (size_t)(m0 + ty*8 + i)*NW + n0 + tx*8;
        *(float4*)&Cm[row]   = *(float4*)&acc[i][0];
        *(float4*)&Cm[row+4] = *(float4*)&acc[i][4];
    }
}

// ---------------- in-place rotary on g_q and g_k ----------------
// element q[b,c, n*HD+d, w]; interleaved pairs (d even, d+1), angle = w * 10000^{-d/HD}
__global__ void __launch_bounds__(256) rotary_kernel()
{
    size_t idx = (size_t)blockIdx.x * blockDim.x + threadIdx.x;
    if (idx >= TENS/2) return;
    int w    = (int)(idx % NW);
    size_t t = idx / NW;
    int fp = (int)(t % (NF/2));
    int bc = (int)(t / (NF/2));
    int f  = fp * 2;
    int d  = f & (NHD - 1);
    float inv = powf(10000.f, -(float)d / (float)NHD);
    float th  = (float)w * inv;
    float sn, cs;
    sincosf(th, &sn, &cs);
    size_t i0 = ((size_t)bc*NF + f)*NW + w;
    size_t i1 = i0 + NW;
    float x1 = g_q[i0], x2 = g_q[i1];
    g_q[i0] = x1*cs - x2*sn;
    g_q[i1] = x2*cs + x1*sn;
    x1 = g_k[i0]; x2 = g_k[i1];
    g_k[i0] = x1*cs - x2*sn;
    g_k[i1] = x2*cs + x1*sn;
}

// ---------------- QK^T logits: S = Q^T K / 32 + prev ----------------
// per head (z = bc*NH + n): Q,K are [HD x W] slabs (d slow, w contiguous)
__global__ void __launch_bounds__(256) qk_kernel(
    const float* __restrict__ prev, float* __restrict__ qkout)
{
    __shared__ float As[8][128];
    __shared__ float Bs[8][128];
    int hz = blockIdx.z;
    int bc = hz >> 3, n = hz & 7;
    const float* Q = g_q + ((size_t)bc*NF + n*NHD)*NW;
    const float* K = g_k + ((size_t)bc*NF + n*NHD)*NW;
    int m0 = blockIdx.y * 128;   // qw tile
    int n0 = blockIdx.x * 128;   // kw tile
    int tid = threadIdx.x;
    int ty = tid >> 4, tx = tid & 15;
    int lrow = tid >> 5, lcol = (tid & 31) * 4;

    float acc[8][8] = {};
    for (int k0 = 0; k0 < NHD; k0 += 8) {
        *(float4*)&As[lrow][lcol] = *(const float4*)&Q[(size_t)(k0+lrow)*NW + m0 + lcol];
        *(float4*)&Bs[lrow][lcol] = *(const float4*)&K[(size_t)(k0+lrow)*NW + n0 + lcol];
        __syncthreads();
        #pragma unroll
        for (int kk = 0; kk < 8; ++kk) {
            float a[8], bb[8];
            *(float4*)&a[0]  = *(const float4*)&As[kk][ty*8];
            *(float4*)&a[4]  = *(const float4*)&As[kk][ty*8+4];
            *(float4*)&bb[0] = *(const float4*)&Bs[kk][tx*8];
            *(float4*)&bb[4] = *(const float4*)&Bs[kk][tx*8+4];
            #pragma unroll
            for (int i = 0; i < 8; ++i)
                #pragma unroll
                for (int j = 0; j < 8; ++j)
                    acc[i][j] += a[i]*bb[j];
        }
        __syncthreads();
    }
    const float scale = 1.0f / 32.0f;   // 1/sqrt(F)=1/sqrt(1024)
    size_t base = ((size_t)hz * NW + m0) * NW + n0;
    #pragma unroll
    for (int i = 0; i < 8; ++i) {
        size_t r = base + (size_t)(ty*8+i)*NW + tx*8;
        float4 p0 = *(const float4*)&prev[r];
        float4 p1 = *(const float4*)&prev[r+4];
        float4 o0, o1;
        o0.x = acc[i][0]*scale + p0.x; o0.y = acc[i][1]*scale + p0.y;
        o0.z = acc[i][2]*scale + p0.z; o0.w = acc[i][3]*scale + p0.w;
        o1.x = acc[i][4]*scale + p1.x; o1.y = acc[i][5]*scale + p1.y;
        o1.z = acc[i][6]*scale + p1.z; o1.w = acc[i][7]*scale + p1.w;
        *(float4*)&qkout[r]   = o0;
        *(float4*)&qkout[r+4] = o1;
    }
}

// ---------------- softmax(S) @ V -> g_a ----------------
// block = (qtile of 32 rows, head). dyn smem: Ps[32][513] | Vs[32][132]
#define PS_LD 513
#define VS_LD 132
__global__ void __launch_bounds__(256) softmax_pv_kernel(const float* __restrict__ qk)
{
    extern __shared__ float sm[];
    float* Ps = sm;                       // [32][PS_LD]
    float* Vs = sm + 32*PS_LD;            // [32][VS_LD]  (Vs[kk][d])
    __shared__ float linv[32];
    int hz = blockIdx.y;
    int qt = blockIdx.x;
    int bc = hz >> 3, n = hz & 7;
    int qw0 = qt * 32;
    const float* S = qk  + ((size_t)hz * NW + qw0) * NW;
    const float* V = g_v + ((size_t)bc*NF + n*NHD)*NW;
    float* Aout    = g_a + ((size_t)bc*NF + n*NHD)*NW;
    int tid = threadIdx.x;

    // load S tile (coalesced)
    for (int i = tid; i < 32*NW; i += 256) {
        int r = i >> 9, c = i & 511;
        Ps[r*PS_LD + c] = S[(size_t)r*NW + c];
    }
    __syncthreads();
    // rowwise softmax (8 threads per row)
    {
        int row = tid >> 3, l8 = tid & 7;
        float m = -1e30f;
        for (int j = l8; j < NW; j += 8) m = fmaxf(m, Ps[row*PS_LD + j]);
        #pragma unroll
        for (int o = 4; o; o >>= 1) m = fmaxf(m, __shfl_xor_sync(0xffffffffu, m, o));
        float s = 0.f;
        for (int j = l8; j < NW; j += 8) {
            float e = __expf(Ps[row*PS_LD + j] - m);
            Ps[row*PS_LD + j] = e;
            s += e;
        }
        #pragma unroll
        for (int o = 4; o; o >>= 1) s += __shfl_xor_sync(0xffffffffu, s, o);
        if (l8 == 0) linv[row] = 1.f / s;
    }
    __syncthreads();

    // a[qw, d] = sum_kw P[qw,kw] * V[d,kw]
    float acc[4][4] = {};
    int ty = tid >> 5, tx = tid & 31;    // ty: 4 qw rows, tx: 4 d cols
    for (int kw0 = 0; kw0 < NW; kw0 += 32) {
        #pragma unroll
        for (int rep = 0; rep < 4; ++rep) {
            int lin = tid + rep*256;
            int d  = lin >> 3;
            int kq = (lin & 7) * 4;
            float4 v = *(const float4*)&V[(size_t)d*NW + kw0 + kq];
            Vs[(kq+0)*VS_LD + d] = v.x;
            Vs[(kq+1)*VS_LD + d] = v.y;
            Vs[(kq+2)*VS_LD + d] = v.z;
            Vs[(kq+3)*VS_LD + d] = v.w;
        }
        __syncthreads();
        #pragma unroll
        for (int kk = 0; kk < 32; ++kk) {
            float4 vv = *(const float4*)&Vs[kk*VS_LD + tx*4];
            float p0 = Ps[(ty*4+0)*PS_LD + kw0+kk];
            float p1 = Ps[(ty*4+1)*PS_LD + kw0+kk];
            float p2 = Ps[(ty*4+2)*PS_LD + kw0+kk];
            float p3 = Ps[(ty*4+3)*PS_LD + kw0+kk];
            acc[0][0]+=p0*vv.x; acc[0][1]+=p0*vv.y; acc[0][2]+=p0*vv.z; acc[0][3]+=p0*vv.w;
            acc[1][0]+=p1*vv.x; acc[1][1]+=p1*vv.y; acc[1][2]+=p1*vv.z; acc[1][3]+=p1*vv.w;
            acc[2][0]+=p2*vv.x; acc[2][1]+=p2*vv.y; acc[2][2]+=p2*vv.z; acc[2][3]+=p2*vv.w;
            acc[3][0]+=p3*vv.x; acc[3][1]+=p3*vv.y; acc[3][2]+=p3*vv.z; acc[3][3]+=p3*vv.w;
        }
        __syncthreads();
    }
    // transpose through smem so g_a writes are coalesced: a stored as [d][qw]
    float* At = sm;   // reuse Ps region: [128][33]
    #pragma unroll
    for (int i = 0; i < 4; ++i) {
        float l = linv[ty*4 + i];
        #pragma unroll
        for (int j = 0; j < 4; ++j)
            At[(tx*4+j)*33 + ty*4+i] = acc[i][j] * l;
    }
    __syncthreads();
    for (int idx = tid; idx < 128*32; idx += 256) {
        int d = idx >> 5, qw = idx & 31;
        Aout[(size_t)d*NW + qw0 + qw] = At[d*33 + qw];
    }
}

// ---------------- launch ----------------
extern "C" void kernel_launch(void* const* d_in, const int* in_sizes, int n_in,
                              void* d_out, int out_size)
{
    const float* x       = (const float*)d_in[0];
    const float* prevqk  = (const float*)d_in[1];
    const float* wq_conv = (const float*)d_in[2];
    const float* bq_conv = (const float*)d_in[3];
    const float* wq_lin  = (const float*)d_in[4];
    const float* wk_conv = (const float*)d_in[5];
    const float* bk_conv = (const float*)d_in[6];
    const float* wk_lin  = (const float*)d_in[7];
    const float* wv_conv = (const float*)d_in[8];
    const float* bv_conv = (const float*)d_in[9];
    const float* wv_lin  = (const float*)d_in[10];
    const float* wo_lin  = (const float*)d_in[11];
    float* out   = (float*)d_out;
    float* qkout = out + TENS;     // tuple output: (out, qk) concatenated

    // 1) three convs fused
    conv3_kernel<<<dim3(NW/32, NF/32, NB), 256>>>(
        x, wq_conv, bq_conv, wk_conv, bk_conv, wv_conv, bv_conv);

    // 2) mc_linear for q,k,v
    dim3 gg(NW/128, NF/128, NBC);
    gemm_lin<<<gg, 256>>>(wq_lin, 0, 0, nullptr);
    gemm_lin<<<gg, 256>>>(wk_lin, 1, 1, nullptr);
    gemm_lin<<<gg, 256>>>(wv_lin, 2, 2, nullptr);

    // 3) rotary on q,k (in place)
    rotary_kernel<<<(unsigned)((TENS/2 + 255) / 256), 256>>>();

    // 4) QK^T logits -> qk output region
    qk_kernel<<<dim3(NW/128, NW/128, NBC*NHEAD), 256>>>(prevqk, qkout);

    // 5) softmax @ V -> g_a
    int smpv = (32*PS_LD + 32*VS_LD) * (int)sizeof(float);
    cudaFuncSetAttribute(softmax_pv_kernel,
                         cudaFuncAttributeMaxDynamicSharedMemorySize, smpv);
    softmax_pv_kernel<<<dim3(NW/32, NBC*NHEAD), 256, smpv>>>(qkout);

    // 6) output projection mc_linear -> out region
    gemm_lin<<<gg, 256>>>(wo_lin, 3, 3, out);
}

// round 2
// speedup vs baseline: 1.2980x; 1.2980x over previous
#include <cuda_runtime.h>
#include <cuda_bf16.h>
#include <math.h>
#include <stdint.h>

#define NB 2
#define NC 8
#define NF 1024
#define NW 512
#define NHEAD 8
#define NHD 128
#define NBC (NB*NC)
#define TENS ((size_t)NB*NC*NF*NW)          // 8388608
#define WSZ  ((size_t)NC*NF*NF)             // 8388608 per weight tensor

// ---------------- scratch (static device globals; no runtime alloc) ----------------
__device__ __align__(16) __nv_bfloat16 g_cqh[TENS], g_cql[TENS];
__device__ __align__(16) __nv_bfloat16 g_ckh[TENS], g_ckl[TENS];
__device__ __align__(16) __nv_bfloat16 g_cvh[TENS], g_cvl[TENS];
__device__ __align__(16) __nv_bfloat16 g_qh[TENS], g_ql[TENS];
__device__ __align__(16) __nv_bfloat16 g_kh[TENS], g_kl[TENS];
__device__ __align__(16) __nv_bfloat16 g_ah[TENS], g_al[TENS];
__device__ __align__(16) __nv_bfloat16 g_wh[4*WSZ], g_wl[4*WSZ];
__device__ __align__(16) float g_q[TENS], g_k[TENS], g_v[TENS];

// ---------------- helpers ----------------
__device__ __forceinline__ void split_bf16(float x, __nv_bfloat16& h, __nv_bfloat16& l) {
    h = __float2bfloat16(x);
    l = __float2bfloat16(x - __bfloat162float(h));
}
__device__ __forceinline__ uint32_t smem_u32(const void* p) {
    return (uint32_t)__cvta_generic_to_shared(p);
}
__device__ __forceinline__ void cp16(uint32_t dst, const void* src) {
    asm volatile("cp.async.cg.shared.global [%0], [%1], 16;" :: "r"(dst), "l"(src));
}
__device__ __forceinline__ void cp_commit() { asm volatile("cp.async.commit_group;"); }
template<int N> __device__ __forceinline__ void cp_wait() {
    asm volatile("cp.async.wait_group %0;" :: "n"(N));
}
__device__ __forceinline__ void ldsm4(uint32_t r[4], uint32_t addr) {
    asm volatile("ldmatrix.sync.aligned.m8n8.x4.shared.b16 {%0,%1,%2,%3},[%4];"
                 : "=r"(r[0]), "=r"(r[1]), "=r"(r[2]), "=r"(r[3]) : "r"(addr));
}
__device__ __forceinline__ void ldsm4t(uint32_t r[4], uint32_t addr) {
    asm volatile("ldmatrix.sync.aligned.m8n8.x4.trans.shared.b16 {%0,%1,%2,%3},[%4];"
                 : "=r"(r[0]), "=r"(r[1]), "=r"(r[2]), "=r"(r[3]) : "r"(addr));
}
__device__ __forceinline__ void mma16816(float c[4], const uint32_t a[4], uint32_t b0, uint32_t b1) {
    asm volatile("mma.sync.aligned.m16n8k16.row.col.f32.bf16.bf16.f32 "
                 "{%0,%1,%2,%3},{%4,%5,%6,%7},{%8,%9},{%0,%1,%2,%3};"
                 : "+f"(c[0]), "+f"(c[1]), "+f"(c[2]), "+f"(c[3])
                 : "r"(a[0]), "r"(a[1]), "r"(a[2]), "r"(a[3]), "r"(b0), "r"(b1));
}

// ---------------- fused 3x conv2d (3x3, pad 1, C=8 in/out) -> bf16 hi/lo ----------------
__global__ void __launch_bounds__(256) conv3_kernel(
    const float* __restrict__ x,
    const float* __restrict__ wq, const float* __restrict__ bq,
    const float* __restrict__ wk, const float* __restrict__ bk,
    const float* __restrict__ wv, const float* __restrict__ bv)
{
    __shared__ float xs[NC][34][36];
    __shared__ float ws[3*NC*NC*9];
    int tid = threadIdx.x;
    int bxo = blockIdx.x * 32;
    int byo = blockIdx.y * 32;
    int b   = blockIdx.z;

    for (int i = tid; i < NC*NC*9; i += 256) {
        ws[i]             = wq[i];
        ws[NC*NC*9 + i]   = wk[i];
        ws[2*NC*NC*9 + i] = wv[i];
    }
    for (int i = tid; i < NC*34*34; i += 256) {
        int ci = i / (34*34);
        int r  = (i / 34) % 34;
        int cl = i % 34;
        int gy = byo + r - 1, gx = bxo + cl - 1;
        float v = 0.f;
        if (gy >= 0 && gy < NF && gx >= 0 && gx < NW)
            v = x[(((size_t)b*NC + ci)*NF + gy)*NW + gx];
        xs[ci][r][cl] = v;
    }
    __syncthreads();

    #pragma unroll
    for (int p = 0; p < 4; ++p) {
        int pid = tid + p*256;
        int py = pid >> 5, px = pid & 31;
        float aq[NC], ak[NC], av[NC];
        #pragma unroll
        for (int co = 0; co < NC; ++co) { aq[co]=bq[co]; ak[co]=bk[co]; av[co]=bv[co]; }
        #pragma unroll
        for (int ci = 0; ci < NC; ++ci) {
            float w9[9];
            #pragma unroll
            for (int dy = 0; dy < 3; ++dy)
                #pragma unroll
                for (int dx = 0; dx < 3; ++dx)
                    w9[dy*3+dx] = xs[ci][py+dy][px+dx];
            #pragma unroll
            for (int co = 0; co < NC; ++co) {
                int wb = (co*NC + ci)*9;
                float sq=0.f, sk=0.f, sv=0.f;
                #pragma unroll
                for (int t = 0; t < 9; ++t) {
                    sq += w9[t]*ws[wb+t];
                    sk += w9[t]*ws[NC*NC*9 + wb+t];
                    sv += w9[t]*ws[2*NC*NC*9 + wb+t];
                }
                aq[co]+=sq; ak[co]+=sk; av[co]+=sv;
            }
        }
        int gy = byo + py, gx = bxo + px;
        #pragma unroll
        for (int co = 0; co < NC; ++co) {
            size_t o = (((size_t)b*NC+co)*NF + gy)*NW + gx;
            __nv_bfloat16 h, l;
            split_bf16(aq[co], h, l); g_cqh[o]=h; g_cql[o]=l;
            split_bf16(ak[co], h, l); g_ckh[o]=h; g_ckl[o]=l;
            split_bf16(av[co], h, l); g_cvh[o]=h; g_cvl[o]=l;
        }
    }
}

// ---------------- weight conversion: 4x (8,1024,1024) fp32 -> bf16 hi/lo ----------------
__global__ void __launch_bounds__(256) wconvert_kernel(
    const float* __restrict__ w0, const float* __restrict__ w1,
    const float* __restrict__ w2, const float* __restrict__ w3)
{
    size_t i = (size_t)blockIdx.x * blockDim.x + threadIdx.x;
    if (i >= WSZ) return;
    __nv_bfloat16 h, l;
    split_bf16(w0[i], h, l); g_wh[i]         = h; g_wl[i]         = l;
    split_bf16(w1[i], h, l); g_wh[WSZ + i]   = h; g_wl[WSZ + i]   = l;
    split_bf16(w2[i], h, l); g_wh[2*WSZ + i] = h; g_wl[2*WSZ + i] = l;
    split_bf16(w3[i], h, l); g_wh[3*WSZ + i] = h; g_wl[3*WSZ + i] = l;
}

// ---------------- mc_linear batched GEMM via bf16 tensor cores (3x split) ----------------
// C[z][m][n] = sum_k W[z%8][m][k] * B[z][k][n]; M=1024 N=512 K=1024
// CTA 128x128, BK=32, 2-stage cp.async pipeline, 8 warps (4x2), warp tile 32x64.
#define SA_ (128*40)
#define SB_ (32*136)
__global__ void __launch_bounds__(256, 2) gemm_mma(int wsel, int bsel, float* __restrict__ Cext)
{
    extern __shared__ __nv_bfloat16 sm_[];
    __nv_bfloat16* sAh = sm_;
    __nv_bfloat16* sAl = sAh + 2*SA_;
    __nv_bfloat16* sBh = sAl + 2*SA_;
    __nv_bfloat16* sBl = sBh + 2*SB_;

    int z = blockIdx.z;
    const __nv_bfloat16* Ah = g_wh + (size_t)wsel*WSZ + (size_t)(z & 7)*NF*NF;
    const __nv_bfloat16* Al = g_wl + (size_t)wsel*WSZ + (size_t)(z & 7)*NF*NF;
    const __nv_bfloat16 *BhG, *BlG;
    float* Cg;
    switch (bsel) {
        case 0:  BhG = g_cqh; BlG = g_cql; Cg = g_q;  break;
        case 1:  BhG = g_ckh; BlG = g_ckl; Cg = g_k;  break;
        case 2:  BhG = g_cvh; BlG = g_cvl; Cg = g_v;  break;
        default: BhG = g_ah;  BlG = g_al;  Cg = Cext; break;
    }
    const __nv_bfloat16* Bh = BhG + (size_t)z*NF*NW;
    const __nv_bfloat16* Bl = BlG + (size_t)z*NF*NW;
    float* C = Cg + (size_t)z*NF*NW;

    int m0 = blockIdx.y*128, n0 = blockIdx.x*128;
    int tid = threadIdx.x;
    int lane = tid & 31, wrp = tid >> 5;
    int wm = (wrp >> 1)*32, wn = (wrp & 1)*64;

    int arow = tid >> 1, acol = (tid & 1)*16;
    int brow = tid >> 3, bcol = (tid & 7)*8;

    float acc[2][8][4];
    #pragma unroll
    for (int i = 0; i < 2; ++i)
        #pragma unroll
        for (int j = 0; j < 8; ++j)
            #pragma unroll
            for (int t = 0; t < 4; ++t) acc[i][j][t] = 0.f;

    auto load_stage = [&](int s, int k0) {
        {
            const __nv_bfloat16* gh = Ah + (size_t)(m0 + arow)*NF + k0 + acol;
            const __nv_bfloat16* gl = Al + (size_t)(m0 + arow)*NF + k0 + acol;
            uint32_t dh = smem_u32(sAh + s*SA_ + arow*40 + acol);
            uint32_t dl = smem_u32(sAl + s*SA_ + arow*40 + acol);
            cp16(dh, gh); cp16(dh+16, gh+8);
            cp16(dl, gl); cp16(dl+16, gl+8);
        }
        {
            const __nv_bfloat16* gh = Bh + (size_t)(k0 + brow)*NW + n0 + bcol;
            const __nv_bfloat16* gl = Bl + (size_t)(k0 + brow)*NW + n0 + bcol;
            uint32_t dh = smem_u32(sBh + s*SB_ + brow*136 + bcol);
            uint32_t dl = smem_u32(sBl + s*SB_ + brow*136 + bcol);
            cp16(dh, gh); cp16(dh+128, gh+64);
            cp16(dl, gl); cp16(dl+128, gl+64);
        }
    };

    load_stage(0, 0);
    cp_commit();
    const int KT = NF/32;
    for (int kt = 0; kt < KT; ++kt) {
        if (kt + 1 < KT) { load_stage((kt+1)&1, (kt+1)*32); cp_commit(); cp_wait<1>(); }
        else             { cp_wait<0>(); }
        __syncthreads();
        int s = kt & 1;
        const __nv_bfloat16* cAh = sAh + s*SA_;
        const __nv_bfloat16* cAl = sAl + s*SA_;
        const __nv_bfloat16* cBh = sBh + s*SB_;
        const __nv_bfloat16* cBl = sBl + s*SB_;
        #pragma unroll
        for (int ks = 0; ks < 32; ks += 16) {
            uint32_t ahf[2][4], alf[2][4];
            #pragma unroll
            for (int mt = 0; mt < 2; ++mt) {
                int roff = (wm + mt*16 + (lane & 15))*40 + ks + ((lane >> 4) << 3);
                ldsm4(ahf[mt], smem_u32(cAh + roff));
                ldsm4(alf[mt], smem_u32(cAl + roff));
            }
            #pragma unroll
            for (int p = 0; p < 4; ++p) {
                uint32_t bhf[4], blf[4];
                int boff = (ks + (lane & 15))*136 + wn + p*16 + ((lane >> 4) << 3);
                ldsm4t(bhf, smem_u32(cBh + boff));
                ldsm4t(blf, smem_u32(cBl + boff));
                #pragma unroll
                for (int mt = 0; mt < 2; ++mt) {
                    mma16816(acc[mt][2*p],   ahf[mt], bhf[0], bhf[1]);
                    mma16816(acc[mt][2*p],   ahf[mt], blf[0], blf[1]);
                    mma16816(acc[mt][2*p],   alf[mt], bhf[0], bhf[1]);
                    mma16816(acc[mt][2*p+1], ahf[mt], bhf[2], bhf[3]);
                    mma16816(acc[mt][2*p+1], ahf[mt], blf[2], blf[3]);
                    mma16816(acc[mt][2*p+1], alf[mt], bhf[2], bhf[3]);
                }
            }
        }
        __syncthreads();
    }

    #pragma unroll
    for (int mt = 0; mt < 2; ++mt)
        #pragma unroll
        for (int nt = 0; nt < 8; ++nt) {
            int r = m0 + wm + mt*16 + (lane >> 2);
            int c = n0 + wn + nt*8 + (lane & 3)*2;
            *(float2*)&C[(size_t)r*NW + c]     = make_float2(acc[mt][nt][0], acc[mt][nt][1]);
            *(float2*)&C[(size_t)(r+8)*NW + c] = make_float2(acc[mt][nt][2], acc[mt][nt][3]);
        }
}

// ---------------- rotary on g_q/g_k (fp32 in) -> bf16 hi/lo out ----------------
__global__ void __launch_bounds__(256) rotary_kernel()
{
    size_t idx = (size_t)blockIdx.x * blockDim.x + threadIdx.x;
    if (idx >= TENS/2) return;
    int w    = (int)(idx % NW);
    size_t t = idx / NW;
    int fp = (int)(t % (NF/2));
    int bc = (int)(t / (NF/2));
    int f  = fp * 2;
    int d  = f & (NHD - 1);
    float inv = powf(10000.f, -(float)d / (float)NHD);
    float th  = (float)w * inv;
    float sn, cs;
    sincosf(th, &sn, &cs);
    size_t i0 = ((size_t)bc*NF + f)*NW + w;
    size_t i1 = i0 + NW;
    __nv_bfloat16 h, l;
    float x1 = g_q[i0], x2 = g_q[i1];
    float r0 = x1*cs - x2*sn, r1 = x2*cs + x1*sn;
    split_bf16(r0, h, l); g_qh[i0]=h; g_ql[i0]=l;
    split_bf16(r1, h, l); g_qh[i1]=h; g_ql[i1]=l;
    x1 = g_k[i0]; x2 = g_k[i1];
    r0 = x1*cs - x2*sn; r1 = x2*cs + x1*sn;
    split_bf16(r0, h, l); g_kh[i0]=h; g_kl[i0]=l;
    split_bf16(r1, h, l); g_kh[i1]=h; g_kl[i1]=l;
}

// ---------------- QK^T logits via tensor cores: S = Q^T K / 32 + prev ----------------
// Per head: Q,K stored [d][w] (k-major). M=N=512, K=128. CTA 128x128, BK=32.
__global__ void __launch_bounds__(256, 2) qk_mma(
    const float* __restrict__ prev, float* __restrict__ qkout)
{
    extern __shared__ __nv_bfloat16 sm_[];
    __nv_bfloat16* sAh = sm_;
    __nv_bfloat16* sAl = sAh + 2*SB_;
    __nv_bfloat16* sBh = sAl + 2*SB_;
    __nv_bfloat16* sBl = sBh + 2*SB_;

    int hz = blockIdx.z;
    int bc = hz >> 3, hd = hz & 7;
    size_t slab = ((size_t)bc*NF + hd*NHD)*NW;
    const __nv_bfloat16* QhG = g_qh + slab;
    const __nv_bfloat16* QlG = g_ql + slab;
    const __nv_bfloat16* KhG = g_kh + slab;
    const __nv_bfloat16* KlG = g_kl + slab;

    int m0 = blockIdx.y*128, n0 = blockIdx.x*128;
    int tid = threadIdx.x;
    int lane = tid & 31, wrp = tid >> 5;
    int wm = (wrp >> 1)*32, wn = (wrp & 1)*64;

    int lrow = tid >> 3, lcol = (tid & 7)*8;

    float acc[2][8][4];
    #pragma unroll
    for (int i = 0; i < 2; ++i)
        #pragma unroll
        for (int j = 0; j < 8; ++j)
            #pragma unroll
            for (int t = 0; t < 4; ++t) acc[i][j][t] = 0.f;

    auto load_stage = [&](int s, int k0) {
        size_t grow = (size_t)(k0 + lrow)*NW;
        {
            const __nv_bfloat16* gh = QhG + grow + m0 + lcol;
            const __nv_bfloat16* gl = QlG + grow + m0 + lcol;
            uint32_t dh = smem_u32(sAh + s*SB_ + lrow*136 + lcol);
            uint32_t dl = smem_u32(sAl + s*SB_ + lrow*136 + lcol);
            cp16(dh, gh); cp16(dh+128, gh+64);
            cp16(dl, gl); cp16(dl+128, gl+64);
        }
        {
            const __nv_bfloat16* gh = KhG + grow + n0 + lcol;
            const __nv_bfloat16* gl = KlG + grow + n0 + lcol;
            uint32_t dh = smem_u32(sBh + s*SB_ + lrow*136 + lcol);
            uint32_t dl = smem_u32(sBl + s*SB_ + lrow*136 + lcol);
            cp16(dh, gh); cp16(dh+128, gh+64);
            cp16(dl, gl); cp16(dl+128, gl+64);
        }
    };

    load_stage(0, 0);
    cp_commit();
    const int KT = NHD/32;   // 4
    for (int kt = 0; kt < KT; ++kt) {
        if (kt + 1 < KT) { load_stage((kt+1)&1, (kt+1)*32); cp_commit(); cp_wait<1>(); }
        else             { cp_wait<0>(); }
        __syncthreads();
        int s = kt & 1;
        const __nv_bfloat16* cAh = sAh + s*SB_;
        const __nv_bfloat16* cAl = sAl + s*SB_;
        const __nv_bfloat16* cBh = sBh + s*SB_;
        const __nv_bfloat16* cBl = sBl + s*SB_;
        #pragma unroll
        for (int ks = 0; ks < 32; ks += 16) {
            uint32_t ahf[2][4], alf[2][4];
            #pragma unroll
            for (int mt = 0; mt < 2; ++mt) {
                // A fragment from [k][m] layout via trans ldmatrix
                int off = (ks + (lane & 7) + ((lane >> 4) << 3))*136
                        + wm + mt*16 + (((lane >> 3) & 1) << 3);
                ldsm4t(ahf[mt], smem_u32(cAh + off));
                ldsm4t(alf[mt], smem_u32(cAl + off));
            }
            #pragma unroll
            for (int p = 0; p < 4; ++p) {
                uint32_t bhf[4], blf[4];
                int boff = (ks + (lane & 15))*136 + wn + p*16 + ((lane >> 4) << 3);
                ldsm4t(bhf, smem_u32(cBh + boff));
                ldsm4t(blf, smem_u32(cBl + boff));
                #pragma unroll
                for (int mt = 0; mt < 2; ++mt) {
                    mma16816(acc[mt][2*p],   ahf[mt], bhf[0], bhf[1]);
                    mma16816(acc[mt][2*p],   ahf[mt], blf[0], blf[1]);
                    mma16816(acc[mt][2*p],   alf[mt], bhf[0], bhf[1]);
                    mma16816(acc[mt][2*p+1], ahf[mt], bhf[2], bhf[3]);
                    mma16816(acc[mt][2*p+1], ahf[mt], blf[2], blf[3]);
                    mma16816(acc[mt][2*p+1], alf[mt], bhf[2], bhf[3]);
                }
            }
        }
        __syncthreads();
    }

    const float scale = 1.0f / 32.0f;   // 1/sqrt(F)
    size_t base = (size_t)hz * NW * NW;
    #pragma unroll
    for (int mt = 0; mt < 2; ++mt)
        #pragma unroll
        for (int nt = 0; nt < 8; ++nt) {
            int r = m0 + wm + mt*16 + (lane >> 2);
            int c = n0 + wn + nt*8 + (lane & 3)*2;
            size_t o0 = base + (size_t)r*NW + c;
            size_t o1 = base + (size_t)(r+8)*NW + c;
            float2 p0 = *(const float2*)&prev[o0];
            float2 p1 = *(const float2*)&prev[o1];
            *(float2*)&qkout[o0] = make_float2(acc[mt][nt][0]*scale + p0.x,
                                               acc[mt][nt][1]*scale + p0.y);
            *(float2*)&qkout[o1] = make_float2(acc[mt][nt][2]*scale + p1.x,
                                               acc[mt][nt][3]*scale + p1.y);
        }
}

// ---------------- softmax(S) @ V -> bf16 hi/lo a ----------------
#define PS_LD 513
#define VS_LD 132
__global__ void __launch_bounds__(256) softmax_pv_kernel(const float* __restrict__ qk)
{
    extern __shared__ float sm[];
    float* Ps = sm;                       // [32][PS_LD]
    float* Vs = sm + 32*PS_LD;            // [32][VS_LD]
    __shared__ float linv[32];
    int hz = blockIdx.y;
    int qt = blockIdx.x;
    int bc = hz >> 3, n = hz & 7;
    int qw0 = qt * 32;
    const float* S = qk  + ((size_t)hz * NW + qw0) * NW;
    size_t aoff = ((size_t)bc*NF + n*NHD)*NW;
    const float* V = g_v + aoff;
    int tid = threadIdx.x;

    for (int i = tid; i < 32*NW; i += 256) {
        int r = i >> 9, c = i & 511;
        Ps[r*PS_LD + c] = S[(size_t)r*NW + c];
    }
    __syncthreads();
    {
        int row = tid >> 3, l8 = tid & 7;
        float m = -1e30f;
        for (int j = l8; j < NW; j += 8) m = fmaxf(m, Ps[row*PS_LD + j]);
        #pragma unroll
        for (int o = 4; o; o >>= 1) m = fmaxf(m, __shfl_xor_sync(0xffffffffu, m, o));
        float s = 0.f;
        for (int j = l8; j < NW; j += 8) {
            float e = __expf(Ps[row*PS_LD + j] - m);
            Ps[row*PS_LD + j] = e;
            s += e;
        }
        #pragma unroll
        for (int o = 4; o; o >>= 1) s += __shfl_xor_sync(0xffffffffu, s, o);
        if (l8 == 0) linv[row] = 1.f / s;
    }
    __syncthreads();

    float acc[4][4] = {};
    int ty = tid >> 5, tx = tid & 31;
    for (int kw0 = 0; kw0 < NW; kw0 += 32) {
        #pragma unroll
        for (int rep = 0; rep < 4; ++rep) {
            int lin = tid + rep*256;
            int d  = lin >> 3;
            int kq = (lin & 7) * 4;
            float4 v = *(const float4*)&V[(size_t)d*NW + kw0 + kq];
            Vs[(kq+0)*VS_LD + d] = v.x;
            Vs[(kq+1)*VS_LD + d] = v.y;
            Vs[(kq+2)*VS_LD + d] = v.z;
            Vs[(kq+3)*VS_LD + d] = v.w;
        }
        __syncthreads();
        #pragma unroll
        for (int kk = 0; kk < 32; ++kk) {
            float4 vv = *(const float4*)&Vs[kk*VS_LD + tx*4];
            float p0 = Ps[(ty*4+0)*PS_LD + kw0+kk];
            float p1 = Ps[(ty*4+1)*PS_LD + kw0+kk];
            float p2 = Ps[(ty*4+2)*PS_LD + kw0+kk];
            float p3 = Ps[(ty*4+3)*PS_LD + kw0+kk];
            acc[0][0]+=p0*vv.x; acc[0][1]+=p0*vv.y; acc[0][2]+=p0*vv.z; acc[0][3]+=p0*vv.w;
            acc[1][0]+=p1*vv.x; acc[1][1]+=p1*vv.y; acc[1][2]+=p1*vv.z; acc[1][3]+=p1*vv.w;
            acc[2][0]+=p2*vv.x; acc[2][1]+=p2*vv.y; acc[2][2]+=p2*vv.z; acc[2][3]+=p2*vv.w;
            acc[3][0]+=p3*vv.x; acc[3][1]+=p3*vv.y; acc[3][2]+=p3*vv.z; acc[3][3]+=p3*vv.w;
        }
        __syncthreads();
    }
    float* At = sm;   // reuse: [128][33]
    #pragma unroll
    for (int i = 0; i < 4; ++i) {
        float l = linv[ty*4 + i];
        #pragma unroll
        for (int j = 0; j < 4; ++j)
            At[(tx*4+j)*33 + ty*4+i] = acc[i][j] * l;
    }
    __syncthreads();
    for (int idx = tid; idx < 128*32; idx += 256) {
        int d = idx >> 5, qw = idx & 31;
        float vfin = At[d*33 + qw];
        size_t off = aoff + (size_t)d*NW + qw0 + qw;
        __nv_bfloat16 h, l;
        split_bf16(vfin, h, l);
        g_ah[off] = h; g_al[off] = l;
    }
}

// ---------------- launch ----------------
extern "C" void kernel_launch(void* const* d_in, const int* in_sizes, int n_in,
                              void* d_out, int out_size)
{
    const float* x       = (const float*)d_in[0];
    const float* prevqk  = (const float*)d_in[1];
    const float* wq_conv = (const float*)d_in[2];
    const float* bq_conv = (const float*)d_in[3];
    const float* wq_lin  = (const float*)d_in[4];
    const float* wk_conv = (const float*)d_in[5];
    const float* bk_conv = (const float*)d_in[6];
    const float* wk_lin  = (const float*)d_in[7];
    const float* wv_conv = (const float*)d_in[8];
    const float* bv_conv = (const float*)d_in[9];
    const float* wv_lin  = (const float*)d_in[10];
    const float* wo_lin  = (const float*)d_in[11];
    float* out   = (float*)d_out;
    float* qkout = out + TENS;     // tuple output: (out, qk) concatenated

    int smGemm = (4*SA_ + 4*SB_) * 2;   // 75776 bytes
    int smQk   = (8*SB_) * 2;           // 69632 bytes
    int smPv   = (32*PS_LD + 32*VS_LD) * (int)sizeof(float);
    cudaFuncSetAttribute(gemm_mma, cudaFuncAttributeMaxDynamicSharedMemorySize, smGemm);
    cudaFuncSetAttribute(qk_mma,   cudaFuncAttributeMaxDynamicSharedMemorySize, smQk);
    cudaFuncSetAttribute(softmax_pv_kernel, cudaFuncAttributeMaxDynamicSharedMemorySize, smPv);

    // 1) three convs fused -> bf16 hi/lo
    conv3_kernel<<<dim3(NW/32, NF/32, NB), 256>>>(
        x, wq_conv, bq_conv, wk_conv, bk_conv, wv_conv, bv_conv);

    // 2) weight conversion
    wconvert_kernel<<<(unsigned)((WSZ + 255)/256), 256>>>(wq_lin, wk_lin, wv_lin, wo_lin);

    // 3) mc_linear for q,k,v on tensor cores
    dim3 gg(NW/128, NF/128, NBC);
    gemm_mma<<<gg, 256, smGemm>>>(0, 0, nullptr);
    gemm_mma<<<gg, 256, smGemm>>>(1, 1, nullptr);
    gemm_mma<<<gg, 256, smGemm>>>(2, 2, nullptr);

    // 4) rotary on q,k -> bf16 hi/lo
    rotary_kernel<<<(unsigned)((TENS/2 + 255) / 256), 256>>>();

    // 5) QK^T logits -> qk output region
    qk_mma<<<dim3(NW/128, NW/128, NBC*NHEAD), 256, smQk>>>(prevqk, qkout);

    // 6) softmax @ V -> a (bf16 hi/lo)
    softmax_pv_kernel<<<dim3(NW/32, NBC*NHEAD), 256, smPv>>>(qkout);

    // 7) output projection on tensor cores -> out region
    gemm_mma<<<gg, 256, smGemm>>>(3, 3, out);
}